// round 6
// baseline (speedup 1.0000x reference)
#include <cuda_runtime.h>

// Problem constants
#define NBATCH   512
#define DD       64          // state dim
#define WIDTH    128         // MLP width
#define SSEG     120         // steps per delay segment
#define NSTEPS   600
#define NSAVE    601
#define XDIM     129         // 2*D + 1
#define XP       136         // padded stride; two 68-float halves, 16B aligned
#define HALF     68
#define NCHUNK   17          // float4 chunks per half
#define BT       4           // batch rows per block
#define NTHREADS 256
#define NBLOCKS  (NBATCH / BT)   // 128

// Dopri5 tableau (stage j uses AC[j][0..j-1]); CH = both c_i (time offsets) and
// history interpolation coefficient; BCOEF = solution weights.
__constant__ float AC[6][5] = {
    {0.f, 0.f, 0.f, 0.f, 0.f},
    {0.2f, 0.f, 0.f, 0.f, 0.f},
    {(float)(3.0/40.0), (float)(9.0/40.0), 0.f, 0.f, 0.f},
    {(float)(44.0/45.0), (float)(-56.0/15.0), (float)(32.0/9.0), 0.f, 0.f},
    {(float)(19372.0/6561.0), (float)(-25360.0/2187.0), (float)(64448.0/6561.0),
     (float)(-212.0/729.0), 0.f},
    {(float)(9017.0/3168.0), (float)(-355.0/33.0), (float)(46732.0/5247.0),
     (float)(49.0/176.0), (float)(-5103.0/18656.0)}
};
__constant__ float CH[6] = {0.f, 0.2f, 0.3f, 0.8f, (float)(8.0/9.0), 1.0f};
__constant__ float BCOEF[6] = {(float)(35.0/384.0), 0.f, (float)(500.0/1113.0),
                               (float)(125.0/192.0), (float)(-2187.0/6784.0),
                               (float)(11.0/84.0)};

// ---- packed fp32x2 helpers: FFMA2 lanes = even/odd input partial sums ----
__device__ __forceinline__ void fma2(unsigned long long& acc,
                                     unsigned long long w2,
                                     unsigned long long x2) {
    asm("fma.rn.f32x2 %0, %1, %2, %0;" : "+l"(acc) : "l"(w2), "l"(x2));
}
__device__ __forceinline__ float red2(unsigned long long v) {
    float2 r;
    asm("mov.b64 {%0, %1}, %2;" : "=f"(r.x), "=f"(r.y) : "l"(v));
    return r.x + r.y;
}
__device__ __forceinline__ float shx1(float v) {
    return __shfl_xor_sync(0xffffffffu, v, 1);
}

// WID-output layer (L1/L2), 256 threads: thread (j = tid>>1, h = tid&1) computes
// the h-th K-half of output j for all 4 batch rows. Both FFMA2 operands are
// naturally-contiguous SMEM pairs (no packing instructions). Lane-pair
// shfl_xor(1) combines halves. Weight rows read exactly once per layer.
// Layouts: weights [WIDTH][XP] (pads 0), activations plain [BT][XP] (pads 0).
__device__ __forceinline__ void layer_wid(const float* __restrict__ sW,
                                          const float* __restrict__ bias,
                                          const float* __restrict__ xin,
                                          float* __restrict__ xout,
                                          int tid) {
    const int j = tid >> 1;
    const int h = tid & 1;
    unsigned long long a0 = 0ull, a1 = 0ull, a2 = 0ull, a3 = 0ull;
    const ulonglong2* w2 = reinterpret_cast<const ulonglong2*>(sW + j * XP + h * HALF);
    const ulonglong2* x0 = reinterpret_cast<const ulonglong2*>(xin + 0 * XP + h * HALF);
    const ulonglong2* x1 = reinterpret_cast<const ulonglong2*>(xin + 1 * XP + h * HALF);
    const ulonglong2* x2p = reinterpret_cast<const ulonglong2*>(xin + 2 * XP + h * HALF);
    const ulonglong2* x3 = reinterpret_cast<const ulonglong2*>(xin + 3 * XP + h * HALF);
#pragma unroll
    for (int c = 0; c < NCHUNK; ++c) {
        ulonglong2 w = w2[c];
        ulonglong2 p0 = x0[c];
        fma2(a0, w.x, p0.x); fma2(a0, w.y, p0.y);
        ulonglong2 p1 = x1[c];
        fma2(a1, w.x, p1.x); fma2(a1, w.y, p1.y);
        ulonglong2 p2 = x2p[c];
        fma2(a2, w.x, p2.x); fma2(a2, w.y, p2.y);
        ulonglong2 p3 = x3[c];
        fma2(a3, w.x, p3.x); fma2(a3, w.y, p3.y);
    }
    float s0 = red2(a0), s1 = red2(a1), s2 = red2(a2), s3 = red2(a3);
    s0 += shx1(s0); s1 += shx1(s1); s2 += shx1(s2); s3 += shx1(s3);
    if (h == 0) {
        float b = bias[j];
        xout[0 * XP + j] = fmaxf(s0 + b, 0.f);
        xout[1 * XP + j] = fmaxf(s1 + b, 0.f);
        xout[2 * XP + j] = fmaxf(s2 + b, 0.f);
        xout[3 * XP + j] = fmaxf(s3 + b, 0.f);
    }
}

// D-output layer (L3), 256 threads: thread (j = tid>>2, r2 = (tid>>1)&1,
// h = tid&1) computes the h-th K-half of output j for rows {2r2, 2r2+1}.
// No relu. Writes k[4][64].
__device__ __forceinline__ void layer_out(const float* __restrict__ sW3,
                                          const float* __restrict__ sb3,
                                          const float* __restrict__ xin,
                                          float* __restrict__ kout,
                                          int tid) {
    const int j  = tid >> 2;
    const int r2 = (tid >> 1) & 1;
    const int h  = tid & 1;
    unsigned long long a0 = 0ull, a1 = 0ull;
    const ulonglong2* w2 = reinterpret_cast<const ulonglong2*>(sW3 + j * XP + h * HALF);
    const ulonglong2* x0 = reinterpret_cast<const ulonglong2*>(xin + (2 * r2) * XP + h * HALF);
    const ulonglong2* x1 = reinterpret_cast<const ulonglong2*>(xin + (2 * r2 + 1) * XP + h * HALF);
#pragma unroll
    for (int c = 0; c < NCHUNK; ++c) {
        ulonglong2 w = w2[c];
        ulonglong2 p0 = x0[c];
        fma2(a0, w.x, p0.x); fma2(a0, w.y, p0.y);
        ulonglong2 p1 = x1[c];
        fma2(a1, w.x, p1.x); fma2(a1, w.y, p1.y);
    }
    float e0 = red2(a0), e1 = red2(a1);
    e0 += shx1(e0); e1 += shx1(e1);
    if (h == 0) {
        float b = sb3[j];
        kout[(2 * r2) * DD + j]     = e0 + b;
        kout[(2 * r2 + 1) * DD + j] = e1 + b;
    }
}

// Build stage input x = [y_stage, hist, t], plain layout [BT][XP].
__device__ __forceinline__ void build_x(float* __restrict__ sx,
                                        const float* __restrict__ sy,
                                        const float* __restrict__ sk,
                                        int st, float chist,
                                        const float* __restrict__ yp0,
                                        const float* __restrict__ yp1,
                                        float tval, float dtv, int tid) {
    for (int slot = tid; slot < BT * XDIM; slot += NTHREADS) {
        int r = slot / XDIM;
        int i = slot - r * XDIM;
        float v;
        if (i < DD) {
            float s = 0.f;
            for (int jj = 0; jj < st; ++jj)
                s += AC[st][jj] * sk[jj * BT * DD + r * DD + i];
            v = sy[r * DD + i] + dtv * s;
        } else if (i < 2 * DD) {
            int d = i - DD;
            float p0 = yp0[r * DD + d], p1 = yp1[r * DD + d];
            v = p0 + chist * (p1 - p0);
        } else {
            v = tval;
        }
        sx[r * XP + i] = v;
    }
}

extern __shared__ float smem[];

__global__ __launch_bounds__(NTHREADS, 1)
void dde_kernel(const float* __restrict__ ts, const float* __restrict__ y0,
                const float* __restrict__ W1, const float* __restrict__ b1,
                const float* __restrict__ W2, const float* __restrict__ b2,
                const float* __restrict__ W3, const float* __restrict__ b3,
                float* __restrict__ out, long long out_size) {
    // SMEM layout (floats)
    float* sW1 = smem;                        // WIDTH*XP
    float* sW2 = sW1 + WIDTH * XP;            // WIDTH*XP
    float* sW3 = sW2 + WIDTH * XP;            // DD*XP
    float* sb1 = sW3 + DD * XP;               // WIDTH
    float* sb2 = sb1 + WIDTH;                 // WIDTH
    float* sb3 = sb2 + WIDTH;                 // DD
    float* sx  = sb3 + DD;                    // BT*XP
    float* sh1 = sx + BT * XP;                // BT*XP
    float* sh2 = sh1 + BT * XP;               // BT*XP
    float* sk  = sh2 + BT * XP;               // 6*BT*DD
    float* sy  = sk + 6 * BT * DD;            // BT*DD
    float* sy0 = sy + BT * DD;                // BT*DD
    float* syp0 = sy0 + BT * DD;              // BT*DD
    float* syp1 = syp0 + BT * DD;             // BT*DD

    const int tid = threadIdx.x;
    const int b0 = blockIdx.x * BT;

    // Zero padded weight buffers + activation buffers (pads stay 0 forever:
    // pad weights are 0, so pad activations are never read into results, and
    // nothing writes activation pads after this).
    for (int i = tid; i < 2 * WIDTH * XP + DD * XP; i += NTHREADS) sW1[i] = 0.f;
    for (int i = tid; i < 3 * BT * XP; i += NTHREADS) sx[i] = 0.f;
    __syncthreads();

    // Load weights (padded stride XP) + biases.
    for (int idx = tid; idx < WIDTH * XDIM; idx += NTHREADS) {
        int j = idx / XDIM, i = idx - j * XDIM;
        sW1[j * XP + i] = W1[idx];
    }
    for (int idx = tid; idx < WIDTH * WIDTH; idx += NTHREADS) {
        int j = idx >> 7, i = idx & 127;
        sW2[j * XP + i] = W2[idx];
    }
    for (int idx = tid; idx < DD * WIDTH; idx += NTHREADS) {
        int j = idx >> 7, i = idx & 127;
        sW3[j * XP + i] = W3[idx];
    }
    for (int i = tid; i < WIDTH; i += NTHREADS) { sb1[i] = b1[i]; sb2[i] = b2[i]; }
    for (int i = tid; i < DD; i += NTHREADS) sb3[i] = b3[i];

    // Initial state + write ys[:,0,:] = y0.
    for (int idx = tid; idx < BT * DD; idx += NTHREADS) {
        int r = idx >> 6, d = idx & 63;
        float v = y0[(size_t)(b0 + r) * DD + d];
        sy[idx] = v;
        sy0[idx] = v;
        out[(size_t)(b0 + r) * NSAVE * DD + d] = v;
    }
    const float ts0 = ts[0];
    const float dtv = ts[1] - ts[0];
    __syncthreads();

#pragma unroll 1
    for (int step = 0; step < NSTEPS; ++step) {
        const float* yp0;
        const float* yp1;
        if (step < SSEG) {
            yp0 = sy0;
            yp1 = sy0;   // constant-history segment: y(t-tau) = y0
        } else {
            // Dense-output lookup: previous-segment grid points step-S, step-S+1
            // (written by this block >=119 steps ago; __syncthreads gives visibility).
            if (tid < 128) {
                int sel = tid >> 6;       // 0 -> yp0, 1 -> yp1
                int idx = tid & 63;       // float4 slot within [BT][DD]
                int r = idx >> 4, d4 = idx & 15;
                const float4* src = reinterpret_cast<const float4*>(
                    out + (size_t)(b0 + r) * NSAVE * DD + (size_t)(step - SSEG + sel) * DD)
                    + d4;
                float4 v = *src;
                float4* dst = reinterpret_cast<float4*>(sel ? syp1 : syp0);
                dst[idx] = v;
            }
            yp0 = syp0;
            yp1 = syp1;
            __syncthreads();
        }
        const float tbase = ts0 + (float)step * dtv;

#pragma unroll 1
        for (int st = 0; st < 6; ++st) {
            build_x(sx, sy, sk, st, CH[st], yp0, yp1, tbase + CH[st] * dtv, dtv, tid);
            __syncthreads();
            layer_wid(sW1, sb1, sx, sh1, tid);
            __syncthreads();
            layer_wid(sW2, sb2, sh1, sh2, tid);
            __syncthreads();
            layer_out(sW3, sb3, sh2, sk + st * BT * DD, tid);
            __syncthreads();
        }

        // y_{n+1} = y_n + dt * sum_j b_j k_j ; write dense output.
        for (int e = tid; e < BT * DD; e += NTHREADS) {
            float acc = 0.f;
#pragma unroll
            for (int j = 0; j < 6; ++j) acc += BCOEF[j] * sk[j * BT * DD + e];
            float yn = sy[e] + dtv * acc;
            sy[e] = yn;
            int r = e >> 6, d = e & 63;
            out[(size_t)(b0 + r) * NSAVE * DD + (size_t)(step + 1) * DD + d] = yn;
        }
        __syncthreads();
    }

    // num_steps (int 600 cast to output dtype) appended after ys.
    if (blockIdx.x == 0) {
        long long yssz = (long long)NBATCH * NSAVE * DD;
        for (long long i = yssz + tid; i < out_size; i += NTHREADS) out[i] = 600.0f;
    }
}

#define SMEM_FLOATS (2 * WIDTH * XP + DD * XP + 2 * WIDTH + DD \
                     + 3 * BT * XP + 6 * BT * DD + 4 * BT * DD)

extern "C" void kernel_launch(void* const* d_in, const int* in_sizes, int n_in,
                              void* d_out, int out_size) {
    const float* ts = (const float*)d_in[0];
    const float* y0 = (const float*)d_in[1];
    const float* W1 = (const float*)d_in[2];
    const float* b1 = (const float*)d_in[3];
    const float* W2 = (const float*)d_in[4];
    const float* b2 = (const float*)d_in[5];
    const float* W3 = (const float*)d_in[6];
    const float* b3 = (const float*)d_in[7];
    float* out = (float*)d_out;

    size_t smem_bytes = (size_t)SMEM_FLOATS * sizeof(float);
    cudaFuncSetAttribute(dde_kernel, cudaFuncAttributeMaxDynamicSharedMemorySize,
                         (int)smem_bytes);

    dde_kernel<<<NBLOCKS, NTHREADS, smem_bytes>>>(ts, y0, W1, b1, W2, b2, W3, b3,
                                                  out, (long long)out_size);
}

// round 8
// speedup vs baseline: 1.2035x; 1.2035x over previous
#include <cuda_runtime.h>

// Problem constants
#define NBATCH   512
#define DD       64          // state dim
#define WIDTH    128         // MLP width
#define SSEG     120         // steps per delay segment
#define NSTEPS   600
#define NSAVE    601
#define XDIM     129         // 2*D + 1
#define XP       144         // padded stride: two 72-float halves / four 36-float quarters
#define HALFX    72
#define QUARX    36
#define NCHW     18          // float4 chunks per half (L1/L2)
#define NCH3     9           // float4 chunks per quarter (L3)
#define BT       4           // batch rows per block
#define NTHREADS 256
#define NBLOCKS  (NBATCH / BT)   // 128

// Dopri5 tableau (stage j uses AC[j][0..j-1]); CH = both c_i (time offsets) and
// history interpolation coefficient; BCOEF = solution weights.
__constant__ float AC[6][5] = {
    {0.f, 0.f, 0.f, 0.f, 0.f},
    {0.2f, 0.f, 0.f, 0.f, 0.f},
    {(float)(3.0/40.0), (float)(9.0/40.0), 0.f, 0.f, 0.f},
    {(float)(44.0/45.0), (float)(-56.0/15.0), (float)(32.0/9.0), 0.f, 0.f},
    {(float)(19372.0/6561.0), (float)(-25360.0/2187.0), (float)(64448.0/6561.0),
     (float)(-212.0/729.0), 0.f},
    {(float)(9017.0/3168.0), (float)(-355.0/33.0), (float)(46732.0/5247.0),
     (float)(49.0/176.0), (float)(-5103.0/18656.0)}
};
__constant__ float CH[6] = {0.f, 0.2f, 0.3f, 0.8f, (float)(8.0/9.0), 1.0f};
__constant__ float BCOEF[6] = {(float)(35.0/384.0), 0.f, (float)(500.0/1113.0),
                               (float)(125.0/192.0), (float)(-2187.0/6784.0),
                               (float)(11.0/84.0)};

// ---- packed fp32x2 helpers: FFMA2 lanes = even/odd input partial sums ----
__device__ __forceinline__ void fma2(unsigned long long& acc,
                                     unsigned long long w2,
                                     unsigned long long x2) {
    asm("fma.rn.f32x2 %0, %1, %2, %0;" : "+l"(acc) : "l"(w2), "l"(x2));
}
__device__ __forceinline__ unsigned long long pkf2(float a, float b) {
    unsigned long long r;
    asm("mov.b64 %0, {%1, %2};" : "=l"(r) : "f"(a), "f"(b));
    return r;
}
__device__ __forceinline__ float red2(unsigned long long v) {
    float2 r;
    asm("mov.b64 {%0, %1}, %2;" : "=f"(r.x), "=f"(r.y) : "l"(v));
    return r.x + r.y;
}
__device__ __forceinline__ float shx(float v, int m) {
    return __shfl_xor_sync(0xffffffffu, v, m);
}

// WID layer (L1/L2) with REGISTER weights: thread (j = tid>>1, h = tid&1) holds
// the h-th 72-float half of weight row j in wr[] (f32x2-packed). Only 2-address
// broadcast x loads touch SMEM (conflict-free). shfl_xor(1) combines K-halves.
__device__ __forceinline__ void layer_wid_reg(const ulonglong2* __restrict__ wr,
                                              float bias,
                                              const float* __restrict__ xin,
                                              float* __restrict__ xout,
                                              int j, int h) {
    unsigned long long a0 = 0ull, a1 = 0ull, a2 = 0ull, a3 = 0ull;
    const ulonglong2* x0 = reinterpret_cast<const ulonglong2*>(xin + 0 * XP + h * HALFX);
    const ulonglong2* x1 = reinterpret_cast<const ulonglong2*>(xin + 1 * XP + h * HALFX);
    const ulonglong2* x2 = reinterpret_cast<const ulonglong2*>(xin + 2 * XP + h * HALFX);
    const ulonglong2* x3 = reinterpret_cast<const ulonglong2*>(xin + 3 * XP + h * HALFX);
#pragma unroll
    for (int c = 0; c < NCHW; ++c) {
        ulonglong2 w = wr[c];
        ulonglong2 p0 = x0[c]; fma2(a0, w.x, p0.x); fma2(a0, w.y, p0.y);
        ulonglong2 p1 = x1[c]; fma2(a1, w.x, p1.x); fma2(a1, w.y, p1.y);
        ulonglong2 p2 = x2[c]; fma2(a2, w.x, p2.x); fma2(a2, w.y, p2.y);
        ulonglong2 p3 = x3[c]; fma2(a3, w.x, p3.x); fma2(a3, w.y, p3.y);
    }
    float s0 = red2(a0), s1 = red2(a1), s2 = red2(a2), s3 = red2(a3);
    s0 += shx(s0, 1); s1 += shx(s1, 1); s2 += shx(s2, 1); s3 += shx(s3, 1);
    if (h == 0) {
        xout[0 * XP + j] = fmaxf(s0 + bias, 0.f);
        xout[1 * XP + j] = fmaxf(s1 + bias, 0.f);
        xout[2 * XP + j] = fmaxf(s2 + bias, 0.f);
        xout[3 * XP + j] = fmaxf(s3 + bias, 0.f);
    }
}

// Output layer (L3) with REGISTER weights: thread (jq = tid>>2, q = tid&3)
// holds the q-th 36-float quarter of W3 row jq. shfl_xor(1)+shfl_xor(2)
// combine the 4 K-quarters. No relu. Writes k[4][64].
__device__ __forceinline__ void layer_out_reg(const ulonglong2* __restrict__ wr,
                                              float bias,
                                              const float* __restrict__ xin,
                                              float* __restrict__ kout,
                                              int jq, int q) {
    unsigned long long a0 = 0ull, a1 = 0ull, a2 = 0ull, a3 = 0ull;
    const ulonglong2* x0 = reinterpret_cast<const ulonglong2*>(xin + 0 * XP + q * QUARX);
    const ulonglong2* x1 = reinterpret_cast<const ulonglong2*>(xin + 1 * XP + q * QUARX);
    const ulonglong2* x2 = reinterpret_cast<const ulonglong2*>(xin + 2 * XP + q * QUARX);
    const ulonglong2* x3 = reinterpret_cast<const ulonglong2*>(xin + 3 * XP + q * QUARX);
#pragma unroll
    for (int c = 0; c < NCH3; ++c) {
        ulonglong2 w = wr[c];
        ulonglong2 p0 = x0[c]; fma2(a0, w.x, p0.x); fma2(a0, w.y, p0.y);
        ulonglong2 p1 = x1[c]; fma2(a1, w.x, p1.x); fma2(a1, w.y, p1.y);
        ulonglong2 p2 = x2[c]; fma2(a2, w.x, p2.x); fma2(a2, w.y, p2.y);
        ulonglong2 p3 = x3[c]; fma2(a3, w.x, p3.x); fma2(a3, w.y, p3.y);
    }
    float s0 = red2(a0), s1 = red2(a1), s2 = red2(a2), s3 = red2(a3);
    s0 += shx(s0, 1); s0 += shx(s0, 2);
    s1 += shx(s1, 1); s1 += shx(s1, 2);
    s2 += shx(s2, 1); s2 += shx(s2, 2);
    s3 += shx(s3, 1); s3 += shx(s3, 2);
    if (q == 0) {
        kout[0 * DD + jq] = s0 + bias;
        kout[1 * DD + jq] = s1 + bias;
        kout[2 * DD + jq] = s2 + bias;
        kout[3 * DD + jq] = s3 + bias;
    }
}

// Build stage input x = [y_stage, hist, t], plain layout [BT][XP].
__device__ __forceinline__ void build_x(float* __restrict__ sx,
                                        const float* __restrict__ sy,
                                        const float* __restrict__ sk,
                                        int st, float chist,
                                        const float* __restrict__ yp0,
                                        const float* __restrict__ yp1,
                                        float tval, float dtv, int tid) {
    for (int slot = tid; slot < BT * XDIM; slot += NTHREADS) {
        int r = slot / XDIM;
        int i = slot - r * XDIM;
        float v;
        if (i < DD) {
            float s = 0.f;
            for (int jj = 0; jj < st; ++jj)
                s += AC[st][jj] * sk[jj * BT * DD + r * DD + i];
            v = sy[r * DD + i] + dtv * s;
        } else if (i < 2 * DD) {
            int d = i - DD;
            float p0 = yp0[r * DD + d], p1 = yp1[r * DD + d];
            v = p0 + chist * (p1 - p0);
        } else {
            v = tval;
        }
        sx[r * XP + i] = v;
    }
}

extern __shared__ float smem[];

__global__ __launch_bounds__(NTHREADS, 1)
void dde_kernel(const float* __restrict__ ts, const float* __restrict__ y0,
                const float* __restrict__ W1, const float* __restrict__ b1,
                const float* __restrict__ W2, const float* __restrict__ b2,
                const float* __restrict__ W3, const float* __restrict__ b3,
                float* __restrict__ out, long long out_size) {
    // SMEM layout (floats) — activations + state only (~4.3K floats)
    float* sx  = smem;                        // BT*XP
    float* sh1 = sx + BT * XP;                // BT*XP
    float* sh2 = sh1 + BT * XP;               // BT*XP
    float* sk  = sh2 + BT * XP;               // 6*BT*DD
    float* sy  = sk + 6 * BT * DD;            // BT*DD
    float* sy0 = sy + BT * DD;                // BT*DD
    float* syp0 = sy0 + BT * DD;              // BT*DD
    float* syp1 = syp0 + BT * DD;             // BT*DD

    const int tid = threadIdx.x;
    const int b0 = blockIdx.x * BT;
    const int j  = tid >> 1;       // L1/L2 output
    const int h  = tid & 1;        // K-half
    const int jq = tid >> 2;       // L3 output
    const int q  = tid & 3;        // K-quarter

    // ---- Load weights into REGISTERS (persist across all 600 steps) ----
    ulonglong2 w1r[NCHW], w2r[NCHW], w3r[NCH3];
#pragma unroll
    for (int c = 0; c < NCHW; ++c) {
        int base = h * HALFX + 4 * c;
        float f0 = (base + 0 < XDIM) ? W1[j * XDIM + base + 0] : 0.f;
        float f1 = (base + 1 < XDIM) ? W1[j * XDIM + base + 1] : 0.f;
        float f2 = (base + 2 < XDIM) ? W1[j * XDIM + base + 2] : 0.f;
        float f3 = (base + 3 < XDIM) ? W1[j * XDIM + base + 3] : 0.f;
        w1r[c] = make_ulonglong2(pkf2(f0, f1), pkf2(f2, f3));
        float g0 = (base + 0 < WIDTH) ? W2[j * WIDTH + base + 0] : 0.f;
        float g1 = (base + 1 < WIDTH) ? W2[j * WIDTH + base + 1] : 0.f;
        float g2 = (base + 2 < WIDTH) ? W2[j * WIDTH + base + 2] : 0.f;
        float g3 = (base + 3 < WIDTH) ? W2[j * WIDTH + base + 3] : 0.f;
        w2r[c] = make_ulonglong2(pkf2(g0, g1), pkf2(g2, g3));
    }
#pragma unroll
    for (int c = 0; c < NCH3; ++c) {
        int base = q * QUARX + 4 * c;
        float f0 = (base + 0 < WIDTH) ? W3[jq * WIDTH + base + 0] : 0.f;
        float f1 = (base + 1 < WIDTH) ? W3[jq * WIDTH + base + 1] : 0.f;
        float f2 = (base + 2 < WIDTH) ? W3[jq * WIDTH + base + 2] : 0.f;
        float f3 = (base + 3 < WIDTH) ? W3[jq * WIDTH + base + 3] : 0.f;
        w3r[c] = make_ulonglong2(pkf2(f0, f1), pkf2(f2, f3));
    }
    const float bj1 = b1[j];
    const float bj2 = b2[j];
    const float bj3 = b3[jq];

    // Zero activation buffers (pads 129..143 stay 0 forever: build_x writes
    // i<129, layers write col<128, so pad contributions are exactly 0).
    for (int i = tid; i < 3 * BT * XP; i += NTHREADS) sx[i] = 0.f;

    // Initial state + write ys[:,0,:] = y0.
    for (int idx = tid; idx < BT * DD; idx += NTHREADS) {
        int r = idx >> 6, d = idx & 63;
        float v = y0[(size_t)(b0 + r) * DD + d];
        sy[idx] = v;
        sy0[idx] = v;
        out[(size_t)(b0 + r) * NSAVE * DD + d] = v;
    }
    const float ts0 = ts[0];
    const float dtv = ts[1] - ts[0];
    __syncthreads();

#pragma unroll 1
    for (int step = 0; step < NSTEPS; ++step) {
        const float* yp0;
        const float* yp1;
        if (step < SSEG) {
            yp0 = sy0;
            yp1 = sy0;   // constant-history segment: y(t-tau) = y0
        } else {
            // Dense-output lookup: previous-segment grid points step-S, step-S+1
            // (written by this block >=119 steps ago; __syncthreads gives visibility).
            if (tid < 128) {
                int sel = tid >> 6;       // 0 -> yp0, 1 -> yp1
                int idx = tid & 63;       // float4 slot within [BT][DD]
                int r = idx >> 4, d4 = idx & 15;
                const float4* src = reinterpret_cast<const float4*>(
                    out + (size_t)(b0 + r) * NSAVE * DD + (size_t)(step - SSEG + sel) * DD)
                    + d4;
                float4 v = *src;
                float4* dst = reinterpret_cast<float4*>(sel ? syp1 : syp0);
                dst[idx] = v;
            }
            yp0 = syp0;
            yp1 = syp1;
            __syncthreads();
        }
        const float tbase = ts0 + (float)step * dtv;

#pragma unroll 1
        for (int st = 0; st < 6; ++st) {
            build_x(sx, sy, sk, st, CH[st], yp0, yp1, tbase + CH[st] * dtv, dtv, tid);
            __syncthreads();
            layer_wid_reg(w1r, bj1, sx, sh1, j, h);
            __syncthreads();
            layer_wid_reg(w2r, bj2, sh1, sh2, j, h);
            __syncthreads();
            layer_out_reg(w3r, bj3, sh2, sk + st * BT * DD, jq, q);
            __syncthreads();
        }

        // y_{n+1} = y_n + dt * sum_j b_j k_j ; write dense output.
        for (int e = tid; e < BT * DD; e += NTHREADS) {
            float acc = 0.f;
#pragma unroll
            for (int jj = 0; jj < 6; ++jj) acc += BCOEF[jj] * sk[jj * BT * DD + e];
            float yn = sy[e] + dtv * acc;
            sy[e] = yn;
            int r = e >> 6, d = e & 63;
            out[(size_t)(b0 + r) * NSAVE * DD + (size_t)(step + 1) * DD + d] = yn;
        }
        __syncthreads();
    }

    // num_steps (int 600 cast to output dtype) appended after ys.
    if (blockIdx.x == 0) {
        long long yssz = (long long)NBATCH * NSAVE * DD;
        for (long long i = yssz + tid; i < out_size; i += NTHREADS) out[i] = 600.0f;
    }
}

#define SMEM_FLOATS (3 * BT * XP + 6 * BT * DD + 4 * BT * DD)

extern "C" void kernel_launch(void* const* d_in, const int* in_sizes, int n_in,
                              void* d_out, int out_size) {
    const float* ts = (const float*)d_in[0];
    const float* y0 = (const float*)d_in[1];
    const float* W1 = (const float*)d_in[2];
    const float* b1 = (const float*)d_in[3];
    const float* W2 = (const float*)d_in[4];
    const float* b2 = (const float*)d_in[5];
    const float* W3 = (const float*)d_in[6];
    const float* b3 = (const float*)d_in[7];
    float* out = (float*)d_out;

    size_t smem_bytes = (size_t)SMEM_FLOATS * sizeof(float);
    cudaFuncSetAttribute(dde_kernel, cudaFuncAttributeMaxDynamicSharedMemorySize,
                         (int)smem_bytes);

    dde_kernel<<<NBLOCKS, NTHREADS, smem_bytes>>>(ts, y0, W1, b1, W2, b2, W3, b3,
                                                  out, (long long)out_size);
}